// round 3
// baseline (speedup 1.0000x reference)
#include <cuda_runtime.h>
#include <cuda_bf16.h>
#include <cstdint>

#define HIDDEN 3584
#define RDIM   224
#define MAX_TOKENS 16384

// ---------------- scratch (static device allocations) ----------------
__device__ __nv_bfloat16 g_wdp[RDIM * HIDDEN];     // gamma * w_down, bf16  [224][3584]
__device__ __nv_bfloat16 g_wup[HIDDEN * RDIM];     // w_up bf16             [3584][224]
__device__ float         g_c1[RDIM];
__device__ float         g_c2[RDIM];
__device__ __nv_bfloat16 g_mid[(size_t)MAX_TOKENS * RDIM];  // gelu output bf16

// ---------------- helpers ----------------
__device__ __forceinline__ void mma_bf16(float c[4], const uint32_t a[4],
                                         uint32_t b0, uint32_t b1) {
    asm volatile(
        "mma.sync.aligned.m16n8k16.row.col.f32.bf16.bf16.f32 "
        "{%0,%1,%2,%3}, {%4,%5,%6,%7}, {%8,%9}, {%0,%1,%2,%3};\n"
        : "+f"(c[0]), "+f"(c[1]), "+f"(c[2]), "+f"(c[3])
        : "r"(a[0]), "r"(a[1]), "r"(a[2]), "r"(a[3]), "r"(b0), "r"(b1));
}

__device__ __forceinline__ float gelu_exact(float y) {
    return 0.5f * y * (1.0f + erff(y * 0.70710678118654752f));
}

__device__ __forceinline__ void cp16(void* dst_smem, const void* src_gmem) {
    uint32_t d = (uint32_t)__cvta_generic_to_shared(dst_smem);
    asm volatile("cp.async.cg.shared.global [%0], [%1], 16;\n" :: "r"(d), "l"(src_gmem));
}
#define CP_COMMIT() asm volatile("cp.async.commit_group;\n" ::: "memory")
#define CP_WAIT0()  asm volatile("cp.async.wait_group 0;\n" ::: "memory")

// ---------------- prep kernels ----------------
__global__ void prep_down(const float* __restrict__ wd, const float* __restrict__ gamma,
                          const float* __restrict__ beta) {
    int r = blockIdx.x;
    const float* row = wd + (size_t)r * HIDDEN;
    float c1 = 0.f, c2 = 0.f;
    for (int h = threadIdx.x; h < HIDDEN; h += 256) {
        float g = gamma[h], w = row[h];
        g_wdp[(size_t)r * HIDDEN + h] = __float2bfloat16(g * w);
        c1 += g * w;
        c2 += beta[h] * w;
    }
    __shared__ float s1[256], s2[256];
    s1[threadIdx.x] = c1; s2[threadIdx.x] = c2;
    __syncthreads();
    for (int o = 128; o > 0; o >>= 1) {
        if ((int)threadIdx.x < o) {
            s1[threadIdx.x] += s1[threadIdx.x + o];
            s2[threadIdx.x] += s2[threadIdx.x + o];
        }
        __syncthreads();
    }
    if (threadIdx.x == 0) { g_c1[r] = s1[0]; g_c2[r] = s2[0]; }
}

__global__ void prep_up(const float* __restrict__ wu) {
    int i = blockIdx.x * blockDim.x + threadIdx.x;
    if (i < HIDDEN * RDIM) g_wup[i] = __float2bfloat16(wu[i]);
}

// ---------------- kernel 1: fused LN + down-proj + GELU (pipelined) ----------------
#define K1_AS 72
#define K1_ABUF (64 * K1_AS)
#define K1_BBUF (RDIM * K1_AS)
#define K1_NCH  (HIDDEN / 64)   // 56

__global__ __launch_bounds__(256, 2)
void kernel_ln_down(const float* __restrict__ x) {
    extern __shared__ __nv_bfloat16 dsm[];
    __nv_bfloat16* sA = dsm;                    // 2 x [64][K1_AS]
    __nv_bfloat16* sB = dsm + 2 * K1_ABUF;      // 2 x [224][K1_AS]

    __shared__ float sS1[64][4];
    __shared__ float sS2[64][4];
    __shared__ float sMu[64], sRstd[64];
    __shared__ float sC1[RDIM], sC2[RDIM];

    const int tid  = threadIdx.x;
    const int warp = tid >> 5, lane = tid & 31;
    const int gid  = lane >> 2, tig = lane & 3;
    const int wm   = warp >> 2, wn = warp & 3;   // 2(m) x 4(n) warp grid
    const int m0   = blockIdx.x * 64;

    for (int i = tid; i < RDIM; i += 256) { sC1[i] = g_c1[i]; sC2[i] = g_c2[i]; }

    float acc[2][7][4];
#pragma unroll
    for (int a = 0; a < 2; a++)
#pragma unroll
        for (int b = 0; b < 7; b++)
#pragma unroll
            for (int c = 0; c < 4; c++) acc[a][b][c] = 0.f;

    const int lrow = tid >> 2, lq = tid & 3;
    const float* xrow = x + (size_t)(m0 + lrow) * HIDDEN + lq * 16;
    const int brow = tid >> 3, bc8 = tid & 7;
    float s1 = 0.f, s2 = 0.f;

    // ---- prologue: chunk 0 into buffer 0 ----
#pragma unroll
    for (int j = 0; j < 7; j++) {
        int row = brow + j * 32;
        cp16(&sB[row * K1_AS + bc8 * 8], g_wdp + (size_t)row * HIDDEN + bc8 * 8);
    }
    CP_COMMIT();
    {
        float4 v[4];
#pragma unroll
        for (int i = 0; i < 4; i++) v[i] = *(const float4*)(xrow + i * 4);
#pragma unroll
        for (int i = 0; i < 4; i++) {
            s1 += v[i].x + v[i].y + v[i].z + v[i].w;
            s2 += v[i].x * v[i].x + v[i].y * v[i].y + v[i].z * v[i].z + v[i].w * v[i].w;
            __nv_bfloat162* dst = (__nv_bfloat162*)&sA[lrow * K1_AS + lq * 16 + i * 4];
            dst[0] = __floats2bfloat162_rn(v[i].x, v[i].y);
            dst[1] = __floats2bfloat162_rn(v[i].z, v[i].w);
        }
    }
    CP_WAIT0();
    __syncthreads();

    // ---- main pipelined loop ----
    for (int it = 0; it < K1_NCH; it++) {
        const int cur = it & 1, nxt = cur ^ 1;
        const __nv_bfloat16* Ac = sA + cur * K1_ABUF;
        const __nv_bfloat16* Bc = sB + cur * K1_BBUF;

        float4 v[4];
        if (it < K1_NCH - 1) {
            const int ko = (it + 1) * 64;
#pragma unroll
            for (int j = 0; j < 7; j++) {
                int row = brow + j * 32;
                cp16(&sB[nxt * K1_BBUF + row * K1_AS + bc8 * 8],
                     g_wdp + (size_t)row * HIDDEN + ko + bc8 * 8);
            }
            CP_COMMIT();
#pragma unroll
            for (int i = 0; i < 4; i++) v[i] = *(const float4*)(xrow + ko + i * 4);
        }

#pragma unroll
        for (int ks = 0; ks < 4; ks++) {
            const int k0 = ks * 16;
            uint32_t a[2][4];
#pragma unroll
            for (int mt = 0; mt < 2; mt++) {
                const __nv_bfloat16* base =
                    &Ac[(wm * 32 + mt * 16 + gid) * K1_AS + k0 + tig * 2];
                a[mt][0] = *(const uint32_t*)(base);
                a[mt][1] = *(const uint32_t*)(base + 8 * K1_AS);
                a[mt][2] = *(const uint32_t*)(base + 8);
                a[mt][3] = *(const uint32_t*)(base + 8 * K1_AS + 8);
            }
#pragma unroll
            for (int nt = 0; nt < 7; nt++) {
                const int col = wn * 56 + nt * 8 + gid;
                const __nv_bfloat16* bb = &Bc[col * K1_AS + k0 + tig * 2];
                uint32_t b0 = *(const uint32_t*)(bb);
                uint32_t b1 = *(const uint32_t*)(bb + 8);
                mma_bf16(acc[0][nt], a[0], b0, b1);
                mma_bf16(acc[1][nt], a[1], b0, b1);
            }
        }

        if (it < K1_NCH - 1) {
#pragma unroll
            for (int i = 0; i < 4; i++) {
                s1 += v[i].x + v[i].y + v[i].z + v[i].w;
                s2 += v[i].x * v[i].x + v[i].y * v[i].y + v[i].z * v[i].z + v[i].w * v[i].w;
                __nv_bfloat162* dst =
                    (__nv_bfloat162*)&sA[nxt * K1_ABUF + lrow * K1_AS + lq * 16 + i * 4];
                dst[0] = __floats2bfloat162_rn(v[i].x, v[i].y);
                dst[1] = __floats2bfloat162_rn(v[i].z, v[i].w);
            }
            CP_WAIT0();
            __syncthreads();
        }
    }

    // ---- row stats reduction ----
    sS1[lrow][lq] = s1; sS2[lrow][lq] = s2;
    __syncthreads();
    if (tid < 64) {
        float t1 = sS1[tid][0] + sS1[tid][1] + sS1[tid][2] + sS1[tid][3];
        float t2 = sS2[tid][0] + sS2[tid][1] + sS2[tid][2] + sS2[tid][3];
        float mu = t1 * (1.0f / HIDDEN);
        float var = t2 * (1.0f / HIDDEN) - mu * mu;
        sMu[tid] = mu;
        sRstd[tid] = rsqrtf(var + 1e-5f);
    }
    __syncthreads();

    // ---- epilogue: LN correction + GELU + store bf16 ----
#pragma unroll
    for (int mt = 0; mt < 2; mt++) {
        const int r0 = wm * 32 + mt * 16 + gid;
        const float mu0 = sMu[r0],     rs0 = sRstd[r0];
        const float mu1 = sMu[r0 + 8], rs1 = sRstd[r0 + 8];
#pragma unroll
        for (int nt = 0; nt < 7; nt++) {
            const int c = wn * 56 + nt * 8 + tig * 2;
            const float c1a = sC1[c], c1b = sC1[c + 1];
            const float c2a = sC2[c], c2b = sC2[c + 1];
            float y00 = rs0 * (acc[mt][nt][0] - mu0 * c1a) + c2a;
            float y01 = rs0 * (acc[mt][nt][1] - mu0 * c1b) + c2b;
            float y10 = rs1 * (acc[mt][nt][2] - mu1 * c1a) + c2a;
            float y11 = rs1 * (acc[mt][nt][3] - mu1 * c1b) + c2b;
            *(__nv_bfloat162*)&g_mid[(size_t)(m0 + r0) * RDIM + c] =
                __floats2bfloat162_rn(gelu_exact(y00), gelu_exact(y01));
            *(__nv_bfloat162*)&g_mid[(size_t)(m0 + r0 + 8) * RDIM + c] =
                __floats2bfloat162_rn(gelu_exact(y10), gelu_exact(y11));
        }
    }
}

// ---------------- kernel 2: persistent up-proj + residual ----------------
// Grid (5 token-splits, 56 n-blocks) = 280 CTAs == one wave @ 2 CTAs/SM.
// Each CTA: w_up 64-col slice resident in smem; loops over 64-token m-tiles
// with double-buffered cp.async A and register-prefetched epilogue x.
#define K2_AS 232
#define K2_NSPLIT 5
#define K2_ABUF (64 * K2_AS)

__global__ __launch_bounds__(256, 2)
void kernel_up_res(const float* __restrict__ x, const float* __restrict__ alpha_p,
                   float* __restrict__ out, int m_tiles_total) {
    extern __shared__ __nv_bfloat16 smem[];
    __nv_bfloat16* sB = smem;                   // [64][K2_AS]    w_up slice (persistent)
    __nv_bfloat16* sA = smem + K2_ABUF;         // 2 x [64][K2_AS] g tiles

    const int tid  = threadIdx.x;
    const int warp = tid >> 5, lane = tid & 31;
    const int gid  = lane >> 2, tig = lane & 3;
    const int wm   = warp >> 2, wn = warp & 3;   // 2(m) x 4(n) warp grid
    const int n0   = blockIdx.y * 64;
    const int t_begin = (blockIdx.x * m_tiles_total) / K2_NSPLIT;
    const int t_end   = ((blockIdx.x + 1) * m_tiles_total) / K2_NSPLIT;

    const float alpha = __ldg(alpha_p);

    // ---- one-time B load + first A tile ----
#pragma unroll
    for (int j = 0; j < 7; j++) {
        int idx = tid + j * 256;                 // 64 rows x 28 chunks
        int row = idx / 28, c = idx % 28;
        cp16(&sB[row * K2_AS + c * 8], g_wup + (size_t)(n0 + row) * RDIM + c * 8);
    }
    {
        const int m0 = t_begin * 64;
#pragma unroll
        for (int j = 0; j < 7; j++) {
            int idx = tid + j * 256;
            int row = idx / 28, c = idx % 28;
            cp16(&sA[row * K2_AS + c * 8], g_mid + (size_t)(m0 + row) * RDIM + c * 8);
        }
    }
    CP_COMMIT();
    CP_WAIT0();
    __syncthreads();

    for (int t = t_begin; t < t_end; t++) {
        const int cur = (t - t_begin) & 1, nxt = cur ^ 1;
        const int m0 = t * 64;
        const __nv_bfloat16* Ac = sA + cur * K2_ABUF;

        // ---- prefetch epilogue x into registers ----
        float2 xv[2][2][2];
#pragma unroll
        for (int mt = 0; mt < 2; mt++) {
            const int r0 = m0 + wm * 32 + mt * 16 + gid;
#pragma unroll
            for (int nt = 0; nt < 2; nt++) {
                const int c = n0 + wn * 16 + nt * 8 + tig * 2;
                const size_t i0 = (size_t)r0 * HIDDEN + c;
                xv[mt][nt][0] = *(const float2*)(x + i0);
                xv[mt][nt][1] = *(const float2*)(x + i0 + (size_t)8 * HIDDEN);
            }
        }

        // ---- prefetch next A tile ----
        if (t + 1 < t_end) {
            const int m1 = (t + 1) * 64;
#pragma unroll
            for (int j = 0; j < 7; j++) {
                int idx = tid + j * 256;
                int row = idx / 28, c = idx % 28;
                cp16(&sA[nxt * K2_ABUF + row * K2_AS + c * 8],
                     g_mid + (size_t)(m1 + row) * RDIM + c * 8);
            }
            CP_COMMIT();
        }

        // ---- MMA over full K=224 ----
        float acc[2][2][4];
#pragma unroll
        for (int a = 0; a < 2; a++)
#pragma unroll
            for (int b = 0; b < 2; b++)
#pragma unroll
                for (int c = 0; c < 4; c++) acc[a][b][c] = 0.f;

#pragma unroll
        for (int ks = 0; ks < 14; ks++) {
            const int k0 = ks * 16;
            uint32_t a[2][4];
#pragma unroll
            for (int mt = 0; mt < 2; mt++) {
                const __nv_bfloat16* base =
                    &Ac[(wm * 32 + mt * 16 + gid) * K2_AS + k0 + tig * 2];
                a[mt][0] = *(const uint32_t*)(base);
                a[mt][1] = *(const uint32_t*)(base + 8 * K2_AS);
                a[mt][2] = *(const uint32_t*)(base + 8);
                a[mt][3] = *(const uint32_t*)(base + 8 * K2_AS + 8);
            }
#pragma unroll
            for (int nt = 0; nt < 2; nt++) {
                const int col = wn * 16 + nt * 8 + gid;
                const __nv_bfloat16* bb = &sB[col * K2_AS + k0 + tig * 2];
                uint32_t b0 = *(const uint32_t*)(bb);
                uint32_t b1 = *(const uint32_t*)(bb + 8);
                mma_bf16(acc[0][nt], a[0], b0, b1);
                mma_bf16(acc[1][nt], a[1], b0, b1);
            }
        }

        // ---- epilogue: residual add + store ----
#pragma unroll
        for (int mt = 0; mt < 2; mt++) {
            const int r0 = m0 + wm * 32 + mt * 16 + gid;
#pragma unroll
            for (int nt = 0; nt < 2; nt++) {
                const int c = n0 + wn * 16 + nt * 8 + tig * 2;
                const size_t i0 = (size_t)r0 * HIDDEN + c;
                const size_t i1 = i0 + (size_t)8 * HIDDEN;
                float2 o0, o1;
                o0.x = xv[mt][nt][0].x + alpha * acc[mt][nt][0];
                o0.y = xv[mt][nt][0].y + alpha * acc[mt][nt][1];
                o1.x = xv[mt][nt][1].x + alpha * acc[mt][nt][2];
                o1.y = xv[mt][nt][1].y + alpha * acc[mt][nt][3];
                *(float2*)(out + i0) = o0;
                *(float2*)(out + i1) = o1;
            }
        }

        if (t + 1 < t_end) {
            CP_WAIT0();
            __syncthreads();
        }
    }
}

// ---------------- launch ----------------
extern "C" void kernel_launch(void* const* d_in, const int* in_sizes, int n_in,
                              void* d_out, int out_size) {
    const float* x     = (const float*)d_in[0];
    const float* gamma = (const float*)d_in[1];
    const float* beta  = (const float*)d_in[2];
    const float* wd    = (const float*)d_in[3];
    const float* wu    = (const float*)d_in[4];
    const float* alpha = (const float*)d_in[5];
    const int tokens = in_sizes[0] / HIDDEN;   // 16384

    prep_down<<<RDIM, 256>>>(wd, gamma, beta);
    prep_up<<<(HIDDEN * RDIM + 255) / 256, 256>>>(wu);

    const int smem1 = 2 * (K1_ABUF + K1_BBUF) * (int)sizeof(__nv_bfloat16);
    cudaFuncSetAttribute(kernel_ln_down, cudaFuncAttributeMaxDynamicSharedMemorySize, smem1);
    kernel_ln_down<<<tokens / 64, 256, smem1>>>(x);

    const int smem2 = 3 * K2_ABUF * (int)sizeof(__nv_bfloat16);
    cudaFuncSetAttribute(kernel_up_res, cudaFuncAttributeMaxDynamicSharedMemorySize, smem2);
    dim3 g2(K2_NSPLIT, HIDDEN / 64);
    kernel_up_res<<<g2, 256, smem2>>>(x, alpha, (float*)d_out, tokens / 64);
}

// round 5
// speedup vs baseline: 1.1480x; 1.1480x over previous
#include <cuda_runtime.h>
#include <cuda_bf16.h>
#include <cstdint>

#define HIDDEN 3584
#define RDIM   224
#define MAX_TOKENS 16384

// ---------------- scratch (static device allocations) ----------------
__device__ __nv_bfloat16 g_wdp[RDIM * HIDDEN];     // gamma * w_down, bf16  [224][3584]
__device__ __nv_bfloat16 g_wup[HIDDEN * RDIM];     // w_up bf16             [3584][224]
__device__ float         g_c1[RDIM];
__device__ float         g_c2[RDIM];
__device__ __nv_bfloat16 g_mid[(size_t)MAX_TOKENS * RDIM];  // gelu output bf16

// ---------------- helpers ----------------
__device__ __forceinline__ uint32_t smem_u32(const void* p) {
    uint32_t a;
    asm("{ .reg .u64 t; cvta.to.shared.u64 t, %1; cvt.u32.u64 %0, t; }" : "=r"(a) : "l"(p));
    return a;
}

__device__ __forceinline__ void mma_bf16(float c[4], const uint32_t a[4],
                                         uint32_t b0, uint32_t b1) {
    asm volatile(
        "mma.sync.aligned.m16n8k16.row.col.f32.bf16.bf16.f32 "
        "{%0,%1,%2,%3}, {%4,%5,%6,%7}, {%8,%9}, {%0,%1,%2,%3};\n"
        : "+f"(c[0]), "+f"(c[1]), "+f"(c[2]), "+f"(c[3])
        : "r"(a[0]), "r"(a[1]), "r"(a[2]), "r"(a[3]), "r"(b0), "r"(b1));
}

__device__ __forceinline__ void ldsm_x4(uint32_t* r, uint32_t addr) {
    asm volatile("ldmatrix.sync.aligned.m8n8.x4.shared.b16 {%0,%1,%2,%3}, [%4];"
                 : "=r"(r[0]), "=r"(r[1]), "=r"(r[2]), "=r"(r[3]) : "r"(addr));
}
__device__ __forceinline__ void ldsm_x2(uint32_t* r, uint32_t addr) {
    asm volatile("ldmatrix.sync.aligned.m8n8.x2.shared.b16 {%0,%1}, [%2];"
                 : "=r"(r[0]), "=r"(r[1]) : "r"(addr));
}

__device__ __forceinline__ float gelu_exact(float y) {
    return 0.5f * y * (1.0f + erff(y * 0.70710678118654752f));
}

__device__ __forceinline__ void cp16(void* dst_smem, const void* src_gmem) {
    uint32_t d = (uint32_t)__cvta_generic_to_shared(dst_smem);
    asm volatile("cp.async.cg.shared.global [%0], [%1], 16;\n" :: "r"(d), "l"(src_gmem));
}
#define CP_COMMIT() asm volatile("cp.async.commit_group;\n" ::: "memory")
#define CP_WAIT0()  asm volatile("cp.async.wait_group 0;\n" ::: "memory")

// ---------------- prep kernels ----------------
__global__ void prep_down(const float* __restrict__ wd, const float* __restrict__ gamma,
                          const float* __restrict__ beta) {
    int r = blockIdx.x;
    const float* row = wd + (size_t)r * HIDDEN;
    float c1 = 0.f, c2 = 0.f;
    for (int h = threadIdx.x; h < HIDDEN; h += 256) {
        float g = gamma[h], w = row[h];
        g_wdp[(size_t)r * HIDDEN + h] = __float2bfloat16(g * w);
        c1 += g * w;
        c2 += beta[h] * w;
    }
    __shared__ float s1[256], s2[256];
    s1[threadIdx.x] = c1; s2[threadIdx.x] = c2;
    __syncthreads();
    for (int o = 128; o > 0; o >>= 1) {
        if ((int)threadIdx.x < o) {
            s1[threadIdx.x] += s1[threadIdx.x + o];
            s2[threadIdx.x] += s2[threadIdx.x + o];
        }
        __syncthreads();
    }
    if (threadIdx.x == 0) { g_c1[r] = s1[0]; g_c2[r] = s2[0]; }
}

__global__ void prep_up(const float* __restrict__ wu) {
    int i = blockIdx.x * blockDim.x + threadIdx.x;
    if (i < HIDDEN * RDIM) g_wup[i] = __float2bfloat16(wu[i]);
}

// ---------------- kernel 1: fused LN + down-proj + GELU (pipelined, LDSM) ----------------
#define K1_AS 72
#define K1_ABUF (64 * K1_AS)
#define K1_BBUF (RDIM * K1_AS)
#define K1_NCH  (HIDDEN / 64)   // 56

__global__ __launch_bounds__(256, 2)
void kernel_ln_down(const float* __restrict__ x) {
    extern __shared__ __nv_bfloat16 dsm[];
    __nv_bfloat16* sA = dsm;                    // 2 x [64][K1_AS]
    __nv_bfloat16* sB = dsm + 2 * K1_ABUF;      // 2 x [224][K1_AS]

    __shared__ float sS1[64][4];
    __shared__ float sS2[64][4];
    __shared__ float sMu[64], sRstd[64];
    __shared__ float sC1[RDIM], sC2[RDIM];

    const int tid  = threadIdx.x;
    const int warp = tid >> 5, lane = tid & 31;
    const int gid  = lane >> 2, tig = lane & 3;
    const int wm   = warp >> 2, wn = warp & 3;   // 2(m) x 4(n) warp grid
    const int m0   = blockIdx.x * 64;

    for (int i = tid; i < RDIM; i += 256) { sC1[i] = g_c1[i]; sC2[i] = g_c2[i]; }

    // ldmatrix per-lane byte offsets
    const uint32_t aU = smem_u32(sA), bU = smem_u32(sB);
    const uint32_t aLane =
        ((uint32_t)((wm * 32 + (lane & 7) + ((lane >> 3) & 1) * 8) * K1_AS
                    + (lane >> 4) * 8)) * 2u;
    uint32_t bPair[4];
    {
        const int kc = ((lane >> 3) & 1) * 8;
#pragma unroll
        for (int p = 0; p < 3; p++) {
            int nr = wn * 56 + p * 16 + (lane & 7) + ((lane >> 4) & 1) * 8;
            bPair[p] = (uint32_t)(nr * K1_AS + kc) * 2u;
        }
        int nr3 = wn * 56 + 48 + (lane & 7);
        bPair[3] = (uint32_t)(nr3 * K1_AS + kc) * 2u;
    }

    float acc[2][7][4];
#pragma unroll
    for (int a = 0; a < 2; a++)
#pragma unroll
        for (int b = 0; b < 7; b++)
#pragma unroll
            for (int c = 0; c < 4; c++) acc[a][b][c] = 0.f;

    const int lrow = tid >> 2, lq = tid & 3;
    const float* xrow = x + (size_t)(m0 + lrow) * HIDDEN + lq * 16;
    const int brow = tid >> 3, bc8 = tid & 7;
    float s1 = 0.f, s2 = 0.f;

    // ---- prologue: chunk 0 into buffer 0 ----
#pragma unroll
    for (int j = 0; j < 7; j++) {
        int row = brow + j * 32;
        cp16(&sB[row * K1_AS + bc8 * 8], g_wdp + (size_t)row * HIDDEN + bc8 * 8);
    }
    CP_COMMIT();
    {
        float4 v[4];
#pragma unroll
        for (int i = 0; i < 4; i++) v[i] = *(const float4*)(xrow + i * 4);
#pragma unroll
        for (int i = 0; i < 4; i++) {
            s1 += v[i].x + v[i].y + v[i].z + v[i].w;
            s2 += v[i].x * v[i].x + v[i].y * v[i].y + v[i].z * v[i].z + v[i].w * v[i].w;
            __nv_bfloat162* dst = (__nv_bfloat162*)&sA[lrow * K1_AS + lq * 16 + i * 4];
            dst[0] = __floats2bfloat162_rn(v[i].x, v[i].y);
            dst[1] = __floats2bfloat162_rn(v[i].z, v[i].w);
        }
    }
    CP_WAIT0();
    __syncthreads();

    // ---- main pipelined loop ----
    for (int it = 0; it < K1_NCH; it++) {
        const int cur = it & 1, nxt = cur ^ 1;
        const uint32_t aCur = aU + (uint32_t)cur * (K1_ABUF * 2);
        const uint32_t bCur = bU + (uint32_t)cur * (K1_BBUF * 2);

        float4 v[4];
        if (it < K1_NCH - 1) {
            const int ko = (it + 1) * 64;
#pragma unroll
            for (int j = 0; j < 7; j++) {
                int row = brow + j * 32;
                cp16(&sB[nxt * K1_BBUF + row * K1_AS + bc8 * 8],
                     g_wdp + (size_t)row * HIDDEN + ko + bc8 * 8);
            }
            CP_COMMIT();
#pragma unroll
            for (int i = 0; i < 4; i++) v[i] = *(const float4*)(xrow + ko + i * 4);
        }

        // compute 4 k16 steps on current buffers (ldmatrix fragment loads)
#pragma unroll
        for (int ks = 0; ks < 4; ks++) {
            const uint32_t kOff = (uint32_t)ks * 32u;   // 16 halves = 32 bytes
            uint32_t a0[4], a1[4];
            ldsm_x4(a0, aCur + aLane + kOff);
            ldsm_x4(a1, aCur + aLane + (uint32_t)(16 * K1_AS * 2) + kOff);
            uint32_t bf[14];
            ldsm_x4(&bf[0],  bCur + bPair[0] + kOff);
            ldsm_x4(&bf[4],  bCur + bPair[1] + kOff);
            ldsm_x4(&bf[8],  bCur + bPair[2] + kOff);
            ldsm_x2(&bf[12], bCur + bPair[3] + kOff);
#pragma unroll
            for (int nt = 0; nt < 7; nt++) {
                mma_bf16(acc[0][nt], a0, bf[2 * nt], bf[2 * nt + 1]);
                mma_bf16(acc[1][nt], a1, bf[2 * nt], bf[2 * nt + 1]);
            }
        }

        if (it < K1_NCH - 1) {
#pragma unroll
            for (int i = 0; i < 4; i++) {
                s1 += v[i].x + v[i].y + v[i].z + v[i].w;
                s2 += v[i].x * v[i].x + v[i].y * v[i].y + v[i].z * v[i].z + v[i].w * v[i].w;
                __nv_bfloat162* dst =
                    (__nv_bfloat162*)&sA[nxt * K1_ABUF + lrow * K1_AS + lq * 16 + i * 4];
                dst[0] = __floats2bfloat162_rn(v[i].x, v[i].y);
                dst[1] = __floats2bfloat162_rn(v[i].z, v[i].w);
            }
            CP_WAIT0();
            __syncthreads();
        }
    }

    // ---- row stats reduction ----
    sS1[lrow][lq] = s1; sS2[lrow][lq] = s2;
    __syncthreads();
    if (tid < 64) {
        float t1 = sS1[tid][0] + sS1[tid][1] + sS1[tid][2] + sS1[tid][3];
        float t2 = sS2[tid][0] + sS2[tid][1] + sS2[tid][2] + sS2[tid][3];
        float mu = t1 * (1.0f / HIDDEN);
        float var = t2 * (1.0f / HIDDEN) - mu * mu;
        sMu[tid] = mu;
        sRstd[tid] = rsqrtf(var + 1e-5f);
    }
    __syncthreads();

    // ---- epilogue: LN correction + GELU + store bf16 ----
#pragma unroll
    for (int mt = 0; mt < 2; mt++) {
        const int r0 = wm * 32 + mt * 16 + gid;
        const float mu0 = sMu[r0],     rs0 = sRstd[r0];
        const float mu1 = sMu[r0 + 8], rs1 = sRstd[r0 + 8];
#pragma unroll
        for (int nt = 0; nt < 7; nt++) {
            const int c = wn * 56 + nt * 8 + tig * 2;
            const float c1a = sC1[c], c1b = sC1[c + 1];
            const float c2a = sC2[c], c2b = sC2[c + 1];
            float y00 = rs0 * (acc[mt][nt][0] - mu0 * c1a) + c2a;
            float y01 = rs0 * (acc[mt][nt][1] - mu0 * c1b) + c2b;
            float y10 = rs1 * (acc[mt][nt][2] - mu1 * c1a) + c2a;
            float y11 = rs1 * (acc[mt][nt][3] - mu1 * c1b) + c2b;
            *(__nv_bfloat162*)&g_mid[(size_t)(m0 + r0) * RDIM + c] =
                __floats2bfloat162_rn(gelu_exact(y00), gelu_exact(y01));
            *(__nv_bfloat162*)&g_mid[(size_t)(m0 + r0 + 8) * RDIM + c] =
                __floats2bfloat162_rn(gelu_exact(y10), gelu_exact(y11));
        }
    }
}

// ---------------- kernel 2: up-proj + residual (64x64 tiles, 3 CTAs/SM, LDSM) ----------------
#define K2_AS 232

__global__ __launch_bounds__(256, 3)
void kernel_up_res(const float* __restrict__ x, const float* __restrict__ alpha_p,
                   float* __restrict__ out) {
    extern __shared__ __nv_bfloat16 smem[];
    __nv_bfloat16* sA = smem;                  // [64][K2_AS]  g tile
    __nv_bfloat16* sB = smem + 64 * K2_AS;     // [64][K2_AS]  w_up tile

    const int tid  = threadIdx.x;
    const int warp = tid >> 5, lane = tid & 31;
    const int gid  = lane >> 2, tig = lane & 3;
    const int wm   = warp >> 2, wn = warp & 3;   // 2(m) x 4(n) warp grid
    const int m0   = blockIdx.x * 64;
    const int n0   = blockIdx.y * 64;

    const float alpha = __ldg(alpha_p);

    // ---- async tile loads (64 rows x 28 16B-chunks each) ----
#pragma unroll
    for (int j = 0; j < 7; j++) {
        int idx = tid + j * 256;
        int row = idx / 28, c = idx % 28;
        cp16(&sA[row * K2_AS + c * 8], g_mid + (size_t)(m0 + row) * RDIM + c * 8);
        cp16(&sB[row * K2_AS + c * 8], g_wup + (size_t)(n0 + row) * RDIM + c * 8);
    }
    CP_COMMIT();

    // ---- prefetch epilogue x into registers ----
    float2 xv[2][2][2];
#pragma unroll
    for (int mt = 0; mt < 2; mt++) {
        const int r0 = m0 + wm * 32 + mt * 16 + gid;
#pragma unroll
        for (int nt = 0; nt < 2; nt++) {
            const int c = n0 + wn * 16 + nt * 8 + tig * 2;
            const size_t i0 = (size_t)r0 * HIDDEN + c;
            xv[mt][nt][0] = *(const float2*)(x + i0);
            xv[mt][nt][1] = *(const float2*)(x + i0 + (size_t)8 * HIDDEN);
        }
    }

    // ldmatrix per-lane byte offsets
    const uint32_t aU = smem_u32(sA), bU = smem_u32(sB);
    const uint32_t aLane =
        ((uint32_t)((wm * 32 + (lane & 7) + ((lane >> 3) & 1) * 8) * K2_AS
                    + (lane >> 4) * 8)) * 2u;
    const uint32_t bLane =
        ((uint32_t)((wn * 16 + (lane & 7) + ((lane >> 4) & 1) * 8) * K2_AS
                    + ((lane >> 3) & 1) * 8)) * 2u;

    float acc[2][2][4];
#pragma unroll
    for (int a = 0; a < 2; a++)
#pragma unroll
        for (int b = 0; b < 2; b++)
#pragma unroll
            for (int c = 0; c < 4; c++) acc[a][b][c] = 0.f;

    CP_WAIT0();
    __syncthreads();

#pragma unroll
    for (int ks = 0; ks < 14; ks++) {
        const uint32_t kOff = (uint32_t)ks * 32u;
        uint32_t a0[4], a1[4], bf[4];
        ldsm_x4(a0, aU + aLane + kOff);
        ldsm_x4(a1, aU + aLane + (uint32_t)(16 * K2_AS * 2) + kOff);
        ldsm_x4(bf, bU + bLane + kOff);
        mma_bf16(acc[0][0], a0, bf[0], bf[1]);
        mma_bf16(acc[0][1], a0, bf[2], bf[3]);
        mma_bf16(acc[1][0], a1, bf[0], bf[1]);
        mma_bf16(acc[1][1], a1, bf[2], bf[3]);
    }

    // ---- epilogue: residual add + store ----
#pragma unroll
    for (int mt = 0; mt < 2; mt++) {
        const int r0 = m0 + wm * 32 + mt * 16 + gid;
#pragma unroll
        for (int nt = 0; nt < 2; nt++) {
            const int c = n0 + wn * 16 + nt * 8 + tig * 2;
            const size_t i0 = (size_t)r0 * HIDDEN + c;
            const size_t i1 = i0 + (size_t)8 * HIDDEN;
            float2 o0, o1;
            o0.x = xv[mt][nt][0].x + alpha * acc[mt][nt][0];
            o0.y = xv[mt][nt][0].y + alpha * acc[mt][nt][1];
            o1.x = xv[mt][nt][1].x + alpha * acc[mt][nt][2];
            o1.y = xv[mt][nt][1].y + alpha * acc[mt][nt][3];
            *(float2*)(out + i0) = o0;
            *(float2*)(out + i1) = o1;
        }
    }
}

// ---------------- launch ----------------
extern "C" void kernel_launch(void* const* d_in, const int* in_sizes, int n_in,
                              void* d_out, int out_size) {
    const float* x     = (const float*)d_in[0];
    const float* gamma = (const float*)d_in[1];
    const float* beta  = (const float*)d_in[2];
    const float* wd    = (const float*)d_in[3];
    const float* wu    = (const float*)d_in[4];
    const float* alpha = (const float*)d_in[5];
    const int tokens = in_sizes[0] / HIDDEN;   // 16384

    prep_down<<<RDIM, 256>>>(wd, gamma, beta);
    prep_up<<<(HIDDEN * RDIM + 255) / 256, 256>>>(wu);

    const int smem1 = 2 * (K1_ABUF + K1_BBUF) * (int)sizeof(__nv_bfloat16);
    cudaFuncSetAttribute(kernel_ln_down, cudaFuncAttributeMaxDynamicSharedMemorySize, smem1);
    kernel_ln_down<<<tokens / 64, 256, smem1>>>(x);

    const int smem2 = 2 * 64 * K2_AS * (int)sizeof(__nv_bfloat16);
    cudaFuncSetAttribute(kernel_up_res, cudaFuncAttributeMaxDynamicSharedMemorySize, smem2);
    dim3 g2(tokens / 64, HIDDEN / 64);
    kernel_up_res<<<g2, 256, smem2>>>(x, alpha, (float*)d_out);
}